// round 8
// baseline (speedup 1.0000x reference)
#include <cuda_runtime.h>
#include <cuda_bf16.h>
#include <cstdint>

// ---------------- problem constants ----------------
#define B_      32
#define E_      5
#define CIN_    256
#define COUT_   256
#define HH      56
#define WW      56
#define HW      (HH * WW)        // 3136
#define M_PER_OC 2304
#define NP      3364             // 58*58 padded pixels
#define KCH     108              // K chunks of 64 (9 shifts * 12 blocks)
#define NTILES  13

// SMEM layout for conv kernel: 4-stage pipeline
#define A_TILE_B 16384           // 128 rows * 128B
#define B_TILE_B 32768           // 256 rows * 128B
#define STAGE_B  (A_TILE_B + B_TILE_B)   // 49152
#define NSTAGE   4
#define SMEM_TOTAL (NSTAGE * STAGE_B)    // 196608

typedef unsigned long long u64;

// ---------------- device globals (no cudaMalloc allowed) ----------------
__device__ int g_expert[B_];
// A matrix: [e][ocb][128 oc][6912 k] bf16, k = (k1k2*12 + cq*3 + kb)*64 + cl
__device__ __nv_bfloat16 g_A[(size_t)E_ * 2 * 128 * 6912];
// padded transposed input: [b][n 3364][c 512] (c: 0-255 hi, 256-511 lo)
__device__ __nv_bfloat16 g_xpt[(size_t)B_ * NP * 512];

// ---------------- helpers ----------------
__device__ __forceinline__ unsigned SWZ(unsigned off) {
    return off ^ ((off >> 3) & 0x70);
}

// L1-bypass async copy (cg): global -> L2 -> smem, no L1 cache allocation
__device__ __forceinline__ void cpa16(unsigned dst, const void* src, unsigned srcsize) {
    asm volatile("cp.async.cg.shared.global [%0], [%1], 16, %2;\n"
                 :: "r"(dst), "l"(src), "r"(srcsize) : "memory");
}

__device__ __forceinline__ void ldsm_x4(unsigned* r, unsigned addr) {
    asm volatile("ldmatrix.sync.aligned.m8n8.x4.shared.b16 {%0,%1,%2,%3}, [%4];"
                 : "=r"(r[0]), "=r"(r[1]), "=r"(r[2]), "=r"(r[3]) : "r"(addr));
}

__device__ __forceinline__ void mma_bf16(float* d, const unsigned* a,
                                         unsigned b0, unsigned b1) {
    asm volatile(
        "mma.sync.aligned.m16n8k16.row.col.f32.bf16.bf16.f32 "
        "{%0,%1,%2,%3}, {%4,%5,%6,%7}, {%8,%9}, {%0,%1,%2,%3};"
        : "+f"(d[0]), "+f"(d[1]), "+f"(d[2]), "+f"(d[3])
        : "r"(a[0]), "r"(a[1]), "r"(a[2]), "r"(a[3]), "r"(b0), "r"(b1));
}

// ---------------------------------------------------------------------------
// Kernel 1: top-1 expert per sample
// ---------------------------------------------------------------------------
__global__ void expert_kernel(const float* __restrict__ scores) {
    int b = threadIdx.x;
    if (b < B_) {
        const float* s = scores + b * E_;
        float best = s[0];
        int bi = 0;
#pragma unroll
        for (int e = 1; e < E_; ++e) {
            float v = s[e];
            if (v > best) { best = v; bi = e; }
        }
        g_expert[b] = bi;
    }
}

// ---------------------------------------------------------------------------
// Kernel 2: build A matrix (agg weight -> bf16 hi/lo, K-ordered for chunks)
// ---------------------------------------------------------------------------
__global__ void abuild_kernel(const float* __restrict__ weight,
                              const float* __restrict__ lora_A,
                              const float* __restrict__ lora_B) {
    int t = blockIdx.x * blockDim.x + threadIdx.x;   // 5*256*2304
    int m    = t % M_PER_OC;
    int rest = t / M_PER_OC;
    int oc   = rest % COUT_;
    int e    = rest / COUT_;
    if (e >= E_) return;

    int j = m / 768, v = m % 768;
    const float* Bp = lora_B + e * 9216 + (3 * oc + j) * 12;
    const float* Ap = lora_A + e * 9216;
    float acc = 0.f;
#pragma unroll
    for (int r = 0; r < 12; ++r) acc += Bp[r] * Ap[r * 768 + v];
    float val = weight[oc * M_PER_OC + m] + 4.0f * acc;

    __nv_bfloat16 hi = __float2bfloat16(val);
    __nv_bfloat16 lo = __float2bfloat16(val - __bfloat162float(hi));

    int ci = m / 9, kk = m % 9;          // kk = k1*3+k2
    int ocb = oc >> 7, ocl = oc & 127;
    int cq = ci >> 6, cl = ci & 63;
    __nv_bfloat16* arow = g_A + ((size_t)(e * 2 + ocb) * 128 + ocl) * 6912;
    int kb_base = kk * 12 + cq * 3;
    arow[(kb_base + 0) * 64 + cl] = hi;   // pairs x_hi
    arow[(kb_base + 1) * 64 + cl] = hi;   // pairs x_lo
    arow[(kb_base + 2) * 64 + cl] = lo;   // pairs x_hi
}

// ---------------------------------------------------------------------------
// Kernel 3: padded, transposed, bf16-split input xp_t[b][n][c]
// ---------------------------------------------------------------------------
__global__ void xprep_kernel(const float* __restrict__ x) {
    __shared__ float tile[64 * 58];
    int cblk = blockIdx.x, y58 = blockIdx.y, b = blockIdx.z;
    int tid = threadIdx.x;
    int y = y58 - 1;
    if (y >= 0 && y < HH) {
        for (int idx = tid; idx < 64 * 58; idx += 256) {
            int c = idx / 58, px = idx % 58;
            int xx = px - 1;
            float v = 0.f;
            if (xx >= 0 && xx < WW)
                v = x[((size_t)(b * CIN_ + cblk * 64 + c)) * HW + y * WW + xx];
            tile[idx] = v;
        }
    } else {
        for (int idx = tid; idx < 64 * 58; idx += 256) tile[idx] = 0.f;
    }
    __syncthreads();
    __nv_bfloat16* dst = g_xpt + ((size_t)b * NP + y58 * 58) * 512 + cblk * 64;
    for (int idx = tid; idx < 58 * 64; idx += 256) {
        int px = idx >> 6, c = idx & 63;
        float v = tile[c * 58 + px];
        __nv_bfloat16 hi = __float2bfloat16(v);
        __nv_bfloat16 lo = __float2bfloat16(v - __bfloat162float(hi));
        dst[(size_t)px * 512 + c] = hi;
        dst[(size_t)px * 512 + 256 + c] = lo;
    }
}

// ---------------------------------------------------------------------------
// K-chunk loader: A 128x64 bf16, B 256x64 bf16, SW128, cp.async.cg
// Balanced: every thread issues 12 x 16B cp.async (A:4, B:8)
// ---------------------------------------------------------------------------
__device__ __forceinline__ void load_chunk(int q, unsigned stage,
                                           const __nv_bfloat16* Abase,
                                           const __nv_bfloat16* Bbase,
                                           int n0, int tid) {
    int k1k2 = q / 12, r = q % 12, cq = r / 3, kb = r % 3;
    int shift = (k1k2 / 3) * 58 + (k1k2 % 3);
    int c0 = ((kb == 1) ? 256 : 0) + cq * 64;
    // A tile: 128 rows x 128B; row = tid>>1, half-row per thread
    {
        int row = tid >> 1;
        int ub  = (tid & 1) * 4;
        const char* arow = (const char*)(Abase + (size_t)row * 6912 + q * 64);
#pragma unroll
        for (int u = 0; u < 4; ++u)
            cpa16(stage + SWZ(row * 128 + (ub + u) * 16), arow + (ub + u) * 16, 16);
    }
    // B tile: 256 rows x 128B; one row per thread
    {
        unsigned bs = stage + A_TILE_B;
        int n = n0 + shift + tid;
        bool ok = (n < NP);
        const char* src = ok ? (const char*)(Bbase + (size_t)n * 512 + c0)
                             : (const char*)Bbase;
        unsigned sz = ok ? 16u : 0u;
#pragma unroll
        for (int u = 0; u < 8; ++u)
            cpa16(bs + SWZ(tid * 128 + u * 16), src + u * 16, sz);
    }
    asm volatile("cp.async.commit_group;" ::: "memory");
}

// ---------------------------------------------------------------------------
// Kernel 4: HMMA implicit-GEMM conv. grid (13, 2, 32), 256 threads.
// CTA: 128 oc x 256 px. Warp grid 2(M)x4(N), warp tile 64x64.
// 4-stage cp.async pipeline, single sync per chunk, loads issued before MMA.
// ---------------------------------------------------------------------------
__global__ __launch_bounds__(256, 1)
void conv_mma_kernel(float* __restrict__ out) {
    extern __shared__ __align__(1024) char smem[];
    const unsigned sbase = (unsigned)__cvta_generic_to_shared(smem);
    const int tid  = threadIdx.x;
    const int lane = tid & 31, wid = tid >> 5;
    const int n0   = blockIdx.x * 256;
    const int ocb  = blockIdx.y;
    const int b    = blockIdx.z;
    const int e    = g_expert[b];

    const __nv_bfloat16* Abase = g_A + (size_t)(e * 2 + ocb) * 128 * 6912;
    const __nv_bfloat16* Bbase = g_xpt + (size_t)b * NP * 512;

    float acc[128];
#pragma unroll
    for (int i = 0; i < 128; ++i) acc[i] = 0.f;

    // warp / lane geometry
    const int wm = wid & 1, wn = wid >> 1;      // 2 x 4 warps
    const int m0 = wm * 64, n0w = wn * 64;
    const int g  = lane >> 3, lr = lane & 7;
    // A frag addressing: g0:(m-lo,k-lo) g1:(m-hi,k-lo) g2:(m-lo,k-hi) g3:(m-hi,k-hi)
    const unsigned a_off0 = (unsigned)((m0 + (g & 1) * 8 + lr) * 128 + (g >> 1) * 16);
    // B frag addressing: g0:(n-lo,k-lo) g1:(n-lo,k-hi) g2:(n-hi,k-lo) g3:(n-hi,k-hi)
    const unsigned b_off0 = (unsigned)((n0w + (g >> 1) * 8 + lr) * 128 + (g & 1) * 16);

    // prologue: fill 3 stages
    load_chunk(0, sbase,               Abase, Bbase, n0, tid);
    load_chunk(1, sbase + STAGE_B,     Abase, Bbase, n0, tid);
    load_chunk(2, sbase + 2 * STAGE_B, Abase, Bbase, n0, tid);

    for (int q = 0; q < KCH; ++q) {
        // ensure group q complete (tail-aware ladder)
        if (q < KCH - 2)
            asm volatile("cp.async.wait_group 2;" ::: "memory");
        else if (q == KCH - 2)
            asm volatile("cp.async.wait_group 1;" ::: "memory");
        else
            asm volatile("cp.async.wait_group 0;" ::: "memory");
        __syncthreads();

        // issue prefetch for q+3 into the stage drained at this barrier
        if (q + 3 < KCH)
            load_chunk(q + 3, sbase + ((q + 3) & 3) * STAGE_B,
                       Abase, Bbase, n0, tid);

        const unsigned st = sbase + (q & 3) * STAGE_B;
#pragma unroll
        for (int ks = 0; ks < 4; ++ks) {
            unsigned ar[16], br[16];
#pragma unroll
            for (int mt = 0; mt < 4; ++mt)
                ldsm_x4(ar + mt * 4, st + SWZ(a_off0 + mt * 2048 + ks * 32));
#pragma unroll
            for (int ntp = 0; ntp < 4; ++ntp)
                ldsm_x4(br + ntp * 4,
                        st + A_TILE_B + SWZ(b_off0 + ntp * 2048 + ks * 32));
#pragma unroll
            for (int mt = 0; mt < 4; ++mt)
#pragma unroll
                for (int nt = 0; nt < 8; ++nt) {
                    int bi = (nt >> 1) * 4 + (nt & 1) * 2;
                    mma_bf16(acc + (mt * 8 + nt) * 4, ar + mt * 4,
                             br[bi], br[bi + 1]);
                }
        }
    }

    // --- epilogue: predicated direct stores ---
    const int qrow = lane >> 2;
    const int qc   = (lane & 3) * 2;
    const size_t ob = (size_t)b * COUT_ * HW;
#pragma unroll
    for (int mt = 0; mt < 4; ++mt) {
        const int mA = ocb * 128 + m0 + mt * 16 + qrow;
        const int mB = mA + 8;
#pragma unroll
        for (int nt = 0; nt < 8; ++nt) {
            const float* a4 = acc + (mt * 8 + nt) * 4;
            int p0 = n0 + n0w + nt * 8 + qc;
            int p1 = p0 + 1;
            int y0 = p0 / 58, x0 = p0 % 58;
            int y1 = p1 / 58, x1 = p1 % 58;
            bool v0 = (y0 < HH) && (x0 < WW);
            bool v1 = (y1 < HH) && (x1 < WW);
            if (v0) out[ob + ((size_t)mA * HH + y0) * WW + x0] = a4[0];
            if (v1) out[ob + ((size_t)mA * HH + y1) * WW + x1] = a4[1];
            if (v0) out[ob + ((size_t)mB * HH + y0) * WW + x0] = a4[2];
            if (v1) out[ob + ((size_t)mB * HH + y1) * WW + x1] = a4[3];
        }
    }
}

// ---------------------------------------------------------------------------
extern "C" void kernel_launch(void* const* d_in, const int* in_sizes, int n_in,
                              void* d_out, int out_size) {
    const float* x      = (const float*)d_in[0];
    const float* scores = (const float*)d_in[1];
    const float* weight = (const float*)d_in[2];
    const float* lora_A = (const float*)d_in[3];
    const float* lora_B = (const float*)d_in[4];
    float* out = (float*)d_out;

    cudaFuncSetAttribute(conv_mma_kernel,
                         cudaFuncAttributeMaxDynamicSharedMemorySize, SMEM_TOTAL);

    expert_kernel<<<1, 32>>>(scores);

    int total = E_ * COUT_ * M_PER_OC;          // 2,949,120
    abuild_kernel<<<total / 256, 256>>>(weight, lora_A, lora_B);

    dim3 xg(4, 58, B_);
    xprep_kernel<<<xg, 256>>>(x);

    dim3 cg(NTILES, 2, B_);
    conv_mma_kernel<<<cg, 256, SMEM_TOTAL>>>(out);
}

// round 9
// speedup vs baseline: 1.2191x; 1.2191x over previous
#include <cuda_runtime.h>
#include <cuda_bf16.h>
#include <cstdint>

// ---------------- problem constants ----------------
#define B_      32
#define E_      5
#define CIN_    256
#define COUT_   256
#define HH      56
#define WW      56
#define HW      (HH * WW)        // 3136
#define M_PER_OC 2304
#define NP      3364             // 58*58 padded pixels
#define KCH     108              // K chunks of 64 (9 shifts * 12 blocks)
#define NTILES  13

// SMEM layout for conv kernel: 4-stage pipeline
#define A_TILE_B 16384           // 128 rows * 128B
#define B_TILE_B 32768           // 256 rows * 128B
#define STAGE_B  (A_TILE_B + B_TILE_B)   // 49152
#define NSTAGE   4
#define SMEM_TOTAL (NSTAGE * STAGE_B)    // 196608

typedef unsigned long long u64;

// ---------------- device globals (no cudaMalloc allowed) ----------------
__device__ int g_expert[B_];
// A matrix: [e][ocb][128 oc][6912 k] bf16, k = (k1k2*12 + cq*3 + kb)*64 + cl
__device__ __nv_bfloat16 g_A[(size_t)E_ * 2 * 128 * 6912];
// padded transposed input: [b][n 3364][c 512] (c: 0-255 hi, 256-511 lo)
__device__ __nv_bfloat16 g_xpt[(size_t)B_ * NP * 512];

// ---------------- helpers ----------------
__device__ __forceinline__ unsigned SWZ(unsigned off) {
    return off ^ ((off >> 3) & 0x70);
}

// L1-allocating async copy (B tile has ~12x L1 reuse across kernel shifts)
__device__ __forceinline__ void cpa16(unsigned dst, const void* src, unsigned srcsize) {
    asm volatile("cp.async.ca.shared.global [%0], [%1], 16, %2;\n"
                 :: "r"(dst), "l"(src), "r"(srcsize) : "memory");
}

__device__ __forceinline__ void ldsm_x4(unsigned* r, unsigned addr) {
    asm volatile("ldmatrix.sync.aligned.m8n8.x4.shared.b16 {%0,%1,%2,%3}, [%4];"
                 : "=r"(r[0]), "=r"(r[1]), "=r"(r[2]), "=r"(r[3]) : "r"(addr));
}

__device__ __forceinline__ void mma_bf16(float* d, const unsigned* a,
                                         unsigned b0, unsigned b1) {
    asm volatile(
        "mma.sync.aligned.m16n8k16.row.col.f32.bf16.bf16.f32 "
        "{%0,%1,%2,%3}, {%4,%5,%6,%7}, {%8,%9}, {%0,%1,%2,%3};"
        : "+f"(d[0]), "+f"(d[1]), "+f"(d[2]), "+f"(d[3])
        : "r"(a[0]), "r"(a[1]), "r"(a[2]), "r"(a[3]), "r"(b0), "r"(b1));
}

// ---------------------------------------------------------------------------
// Kernel 1: top-1 expert per sample
// ---------------------------------------------------------------------------
__global__ void expert_kernel(const float* __restrict__ scores) {
    int b = threadIdx.x;
    if (b < B_) {
        const float* s = scores + b * E_;
        float best = s[0];
        int bi = 0;
#pragma unroll
        for (int e = 1; e < E_; ++e) {
            float v = s[e];
            if (v > best) { best = v; bi = e; }
        }
        g_expert[b] = bi;
    }
}

// ---------------------------------------------------------------------------
// Kernel 2: build A matrix (agg weight -> bf16 hi/lo, K-ordered for chunks)
// ---------------------------------------------------------------------------
__global__ void abuild_kernel(const float* __restrict__ weight,
                              const float* __restrict__ lora_A,
                              const float* __restrict__ lora_B) {
    int t = blockIdx.x * blockDim.x + threadIdx.x;   // 5*256*2304
    int m    = t % M_PER_OC;
    int rest = t / M_PER_OC;
    int oc   = rest % COUT_;
    int e    = rest / COUT_;
    if (e >= E_) return;

    int j = m / 768, v = m % 768;
    const float* Bp = lora_B + e * 9216 + (3 * oc + j) * 12;
    const float* Ap = lora_A + e * 9216;
    float acc = 0.f;
#pragma unroll
    for (int r = 0; r < 12; ++r) acc += Bp[r] * Ap[r * 768 + v];
    float val = weight[oc * M_PER_OC + m] + 4.0f * acc;

    __nv_bfloat16 hi = __float2bfloat16(val);
    __nv_bfloat16 lo = __float2bfloat16(val - __bfloat162float(hi));

    int ci = m / 9, kk = m % 9;          // kk = k1*3+k2
    int ocb = oc >> 7, ocl = oc & 127;
    int cq = ci >> 6, cl = ci & 63;
    __nv_bfloat16* arow = g_A + ((size_t)(e * 2 + ocb) * 128 + ocl) * 6912;
    int kb_base = kk * 12 + cq * 3;
    arow[(kb_base + 0) * 64 + cl] = hi;   // pairs x_hi
    arow[(kb_base + 1) * 64 + cl] = hi;   // pairs x_lo
    arow[(kb_base + 2) * 64 + cl] = lo;   // pairs x_hi
}

// ---------------------------------------------------------------------------
// Kernel 3: padded, transposed, bf16-split input xp_t[b][n][c]
// ---------------------------------------------------------------------------
__global__ void xprep_kernel(const float* __restrict__ x) {
    __shared__ float tile[64 * 58];
    int cblk = blockIdx.x, y58 = blockIdx.y, b = blockIdx.z;
    int tid = threadIdx.x;
    int y = y58 - 1;
    if (y >= 0 && y < HH) {
        for (int idx = tid; idx < 64 * 58; idx += 256) {
            int c = idx / 58, px = idx % 58;
            int xx = px - 1;
            float v = 0.f;
            if (xx >= 0 && xx < WW)
                v = x[((size_t)(b * CIN_ + cblk * 64 + c)) * HW + y * WW + xx];
            tile[idx] = v;
        }
    } else {
        for (int idx = tid; idx < 64 * 58; idx += 256) tile[idx] = 0.f;
    }
    __syncthreads();
    __nv_bfloat16* dst = g_xpt + ((size_t)b * NP + y58 * 58) * 512 + cblk * 64;
    for (int idx = tid; idx < 58 * 64; idx += 256) {
        int px = idx >> 6, c = idx & 63;
        float v = tile[c * 58 + px];
        __nv_bfloat16 hi = __float2bfloat16(v);
        __nv_bfloat16 lo = __float2bfloat16(v - __bfloat162float(hi));
        dst[(size_t)px * 512 + c] = hi;
        dst[(size_t)px * 512 + 256 + c] = lo;
    }
}

// ---------------------------------------------------------------------------
// K-chunk loader (512 threads): every thread issues 6 x 16B cp.async (A:2, B:4)
// ---------------------------------------------------------------------------
__device__ __forceinline__ void load_chunk(int q, unsigned stage,
                                           const __nv_bfloat16* Abase,
                                           const __nv_bfloat16* Bbase,
                                           int n0, int tid) {
    int k1k2 = q / 12, r = q % 12, cq = r / 3, kb = r % 3;
    int shift = (k1k2 / 3) * 58 + (k1k2 % 3);
    int c0 = ((kb == 1) ? 256 : 0) + cq * 64;
    // A tile: 128 rows x 128B; row = tid>>2, quarter-row per thread
    {
        int row = tid >> 2;
        int ub  = (tid & 3) * 2;
        const char* arow = (const char*)(Abase + (size_t)row * 6912 + q * 64);
#pragma unroll
        for (int u = 0; u < 2; ++u)
            cpa16(stage + SWZ(row * 128 + (ub + u) * 16), arow + (ub + u) * 16, 16);
    }
    // B tile: 256 rows x 128B; half-row per thread
    {
        unsigned bs = stage + A_TILE_B;
        int row = tid >> 1;
        int ub  = (tid & 1) * 4;
        int n = n0 + shift + row;
        bool ok = (n < NP);
        const char* src = ok ? (const char*)(Bbase + (size_t)n * 512 + c0)
                             : (const char*)Bbase;
        unsigned sz = ok ? 16u : 0u;
#pragma unroll
        for (int u = 0; u < 4; ++u)
            cpa16(bs + SWZ(row * 128 + (ub + u) * 16), src + (ub + u) * 16, sz);
    }
    asm volatile("cp.async.commit_group;" ::: "memory");
}

// ---------------------------------------------------------------------------
// Kernel 4: HMMA implicit-GEMM conv. grid (13, 2, 32), 512 threads.
// CTA: 128 oc x 256 px. Warp grid 4(M)x4(N), warp tile 32x64.
// 4-stage cp.async pipeline, single sync per chunk, loads issued before MMA.
// ---------------------------------------------------------------------------
__global__ __launch_bounds__(512, 1)
void conv_mma_kernel(float* __restrict__ out) {
    extern __shared__ __align__(1024) char smem[];
    const unsigned sbase = (unsigned)__cvta_generic_to_shared(smem);
    const int tid  = threadIdx.x;
    const int lane = tid & 31, wid = tid >> 5;
    const int n0   = blockIdx.x * 256;
    const int ocb  = blockIdx.y;
    const int b    = blockIdx.z;
    const int e    = g_expert[b];

    const __nv_bfloat16* Abase = g_A + (size_t)(e * 2 + ocb) * 128 * 6912;
    const __nv_bfloat16* Bbase = g_xpt + (size_t)b * NP * 512;

    float acc[64];
#pragma unroll
    for (int i = 0; i < 64; ++i) acc[i] = 0.f;

    // warp / lane geometry: 4(M) x 4(N) warps, warp tile 32(M) x 64(N)
    const int wm = wid & 3, wn = wid >> 2;
    const int m0 = wm * 32, n0w = wn * 64;
    const int g  = lane >> 3, lr = lane & 7;
    // A frag: g0:(m-lo,k-lo) g1:(m-hi,k-lo) g2:(m-lo,k-hi) g3:(m-hi,k-hi)
    const unsigned a_off0 = (unsigned)((m0 + (g & 1) * 8 + lr) * 128 + (g >> 1) * 16);
    // B frag: g0:(n-lo,k-lo) g1:(n-lo,k-hi) g2:(n-hi,k-lo) g3:(n-hi,k-hi)
    const unsigned b_off0 = (unsigned)((n0w + (g >> 1) * 8 + lr) * 128 + (g & 1) * 16);

    // prologue: fill 3 stages
    load_chunk(0, sbase,               Abase, Bbase, n0, tid);
    load_chunk(1, sbase + STAGE_B,     Abase, Bbase, n0, tid);
    load_chunk(2, sbase + 2 * STAGE_B, Abase, Bbase, n0, tid);

    for (int q = 0; q < KCH; ++q) {
        if (q < KCH - 2)
            asm volatile("cp.async.wait_group 2;" ::: "memory");
        else if (q == KCH - 2)
            asm volatile("cp.async.wait_group 1;" ::: "memory");
        else
            asm volatile("cp.async.wait_group 0;" ::: "memory");
        __syncthreads();

        if (q + 3 < KCH)
            load_chunk(q + 3, sbase + ((q + 3) & 3) * STAGE_B,
                       Abase, Bbase, n0, tid);

        const unsigned st = sbase + (q & 3) * STAGE_B;
#pragma unroll
        for (int ks = 0; ks < 4; ++ks) {
            unsigned ar[8], br[16];
#pragma unroll
            for (int mt = 0; mt < 2; ++mt)
                ldsm_x4(ar + mt * 4, st + SWZ(a_off0 + mt * 2048 + ks * 32));
#pragma unroll
            for (int ntp = 0; ntp < 4; ++ntp)
                ldsm_x4(br + ntp * 4,
                        st + A_TILE_B + SWZ(b_off0 + ntp * 2048 + ks * 32));
#pragma unroll
            for (int mt = 0; mt < 2; ++mt)
#pragma unroll
                for (int nt = 0; nt < 8; ++nt) {
                    int bi = (nt >> 1) * 4 + (nt & 1) * 2;
                    mma_bf16(acc + (mt * 8 + nt) * 4, ar + mt * 4,
                             br[bi], br[bi + 1]);
                }
        }
    }

    // --- epilogue: predicated direct stores ---
    const int qrow = lane >> 2;
    const int qc   = (lane & 3) * 2;
    const size_t ob = (size_t)b * COUT_ * HW;
#pragma unroll
    for (int mt = 0; mt < 2; ++mt) {
        const int mA = ocb * 128 + m0 + mt * 16 + qrow;
        const int mB = mA + 8;
#pragma unroll
        for (int nt = 0; nt < 8; ++nt) {
            const float* a4 = acc + (mt * 8 + nt) * 4;
            int p0 = n0 + n0w + nt * 8 + qc;
            int p1 = p0 + 1;
            int y0 = p0 / 58, x0 = p0 % 58;
            int y1 = p1 / 58, x1 = p1 % 58;
            bool v0 = (y0 < HH) && (x0 < WW);
            bool v1 = (y1 < HH) && (x1 < WW);
            if (v0) out[ob + ((size_t)mA * HH + y0) * WW + x0] = a4[0];
            if (v1) out[ob + ((size_t)mA * HH + y1) * WW + x1] = a4[1];
            if (v0) out[ob + ((size_t)mB * HH + y0) * WW + x0] = a4[2];
            if (v1) out[ob + ((size_t)mB * HH + y1) * WW + x1] = a4[3];
        }
    }
}

// ---------------------------------------------------------------------------
extern "C" void kernel_launch(void* const* d_in, const int* in_sizes, int n_in,
                              void* d_out, int out_size) {
    const float* x      = (const float*)d_in[0];
    const float* scores = (const float*)d_in[1];
    const float* weight = (const float*)d_in[2];
    const float* lora_A = (const float*)d_in[3];
    const float* lora_B = (const float*)d_in[4];
    float* out = (float*)d_out;

    cudaFuncSetAttribute(conv_mma_kernel,
                         cudaFuncAttributeMaxDynamicSharedMemorySize, SMEM_TOTAL);

    expert_kernel<<<1, 32>>>(scores);

    int total = E_ * COUT_ * M_PER_OC;          // 2,949,120
    abuild_kernel<<<total / 256, 256>>>(weight, lora_A, lora_B);

    dim3 xg(4, 58, B_);
    xprep_kernel<<<xg, 256>>>(x);

    dim3 cg(NTILES, 2, B_);
    conv_mma_kernel<<<cg, 512, SMEM_TOTAL>>>(out);
}

// round 10
// speedup vs baseline: 1.3850x; 1.1361x over previous
#include <cuda_runtime.h>
#include <cuda_bf16.h>
#include <cstdint>

// ---------------- problem constants ----------------
#define B_      32
#define E_      5
#define CIN_    256
#define COUT_   256
#define HH      56
#define WW      56
#define HW      (HH * WW)        // 3136
#define M_PER_OC 2304
#define NP      3364             // 58*58 padded pixels
#define KCH     108              // 12 groups x 9 shifts
#define NTILES  13

// SMEM: 4 A-stages + 2 B super-tiles
#define A_TILE_B   16384         // 128 rows * 128B
#define BSUP_ROWS  374           // 256 + max shift 118
#define BSUP_B     49152         // 384 rows * 128B (padded)
#define ABUF_OFF   0
#define BBUF_OFF   (4 * A_TILE_B)                 // 65536
#define SMEM_TOTAL (BBUF_OFF + 2 * BSUP_B)        // 163840

typedef unsigned long long u64;

// ---------------- device globals ----------------
__device__ int g_expert[B_];
// A matrix: [e][ocb][128 oc][6912 k], k = ((cq*3+kb)*9 + k1k2)*64 + cl
__device__ __nv_bfloat16 g_A[(size_t)E_ * 2 * 128 * 6912];
// padded transposed input: [b][n 3364][c 512] (c: 0-255 hi, 256-511 lo)
__device__ __nv_bfloat16 g_xpt[(size_t)B_ * NP * 512];

// ---------------- helpers ----------------
__device__ __forceinline__ unsigned SWZ(unsigned off) {
    return off ^ ((off >> 3) & 0x70);
}

__device__ __forceinline__ void cpa16(unsigned dst, const void* src, unsigned srcsize) {
    asm volatile("cp.async.ca.shared.global [%0], [%1], 16, %2;\n"
                 :: "r"(dst), "l"(src), "r"(srcsize) : "memory");
}

__device__ __forceinline__ void ldsm_x4(unsigned* r, unsigned addr) {
    asm volatile("ldmatrix.sync.aligned.m8n8.x4.shared.b16 {%0,%1,%2,%3}, [%4];"
                 : "=r"(r[0]), "=r"(r[1]), "=r"(r[2]), "=r"(r[3]) : "r"(addr));
}

__device__ __forceinline__ void mma_bf16(float* d, const unsigned* a,
                                         unsigned b0, unsigned b1) {
    asm volatile(
        "mma.sync.aligned.m16n8k16.row.col.f32.bf16.bf16.f32 "
        "{%0,%1,%2,%3}, {%4,%5,%6,%7}, {%8,%9}, {%0,%1,%2,%3};"
        : "+f"(d[0]), "+f"(d[1]), "+f"(d[2]), "+f"(d[3])
        : "r"(a[0]), "r"(a[1]), "r"(a[2]), "r"(a[3]), "r"(b0), "r"(b1));
}

// ---------------------------------------------------------------------------
// Kernel 1: top-1 expert per sample
// ---------------------------------------------------------------------------
__global__ void expert_kernel(const float* __restrict__ scores) {
    int b = threadIdx.x;
    if (b < B_) {
        const float* s = scores + b * E_;
        float best = s[0];
        int bi = 0;
#pragma unroll
        for (int e = 1; e < E_; ++e) {
            float v = s[e];
            if (v > best) { best = v; bi = e; }
        }
        g_expert[b] = bi;
    }
}

// ---------------------------------------------------------------------------
// Kernel 2: build A (agg weight -> bf16 hi/lo, GROUP-major K layout)
// ---------------------------------------------------------------------------
__global__ void abuild_kernel(const float* __restrict__ weight,
                              const float* __restrict__ lora_A,
                              const float* __restrict__ lora_B) {
    int t = blockIdx.x * blockDim.x + threadIdx.x;   // 5*256*2304
    int m    = t % M_PER_OC;
    int rest = t / M_PER_OC;
    int oc   = rest % COUT_;
    int e    = rest / COUT_;
    if (e >= E_) return;

    int j = m / 768, v = m % 768;
    const float* Bp = lora_B + e * 9216 + (3 * oc + j) * 12;
    const float* Ap = lora_A + e * 9216;
    float acc = 0.f;
#pragma unroll
    for (int r = 0; r < 12; ++r) acc += Bp[r] * Ap[r * 768 + v];
    float val = weight[oc * M_PER_OC + m] + 4.0f * acc;

    __nv_bfloat16 hi = __float2bfloat16(val);
    __nv_bfloat16 lo = __float2bfloat16(val - __bfloat162float(hi));

    int ci = m / 9, kk = m % 9;          // kk = k1*3+k2
    int ocb = oc >> 7, ocl = oc & 127;
    int cq = ci >> 6, cl = ci & 63;
    __nv_bfloat16* arow = g_A + ((size_t)(e * 2 + ocb) * 128 + ocl) * 6912;
    // group g = cq*3 + slot; chunk = g*9 + kk
    arow[((cq * 3 + 0) * 9 + kk) * 64 + cl] = hi;   // pairs x_hi
    arow[((cq * 3 + 1) * 9 + kk) * 64 + cl] = hi;   // pairs x_lo
    arow[((cq * 3 + 2) * 9 + kk) * 64 + cl] = lo;   // pairs x_hi
}

// ---------------------------------------------------------------------------
// Kernel 3: padded, transposed, bf16-split input xp_t[b][n][c]
// ---------------------------------------------------------------------------
__global__ void xprep_kernel(const float* __restrict__ x) {
    __shared__ float tile[64 * 58];
    int cblk = blockIdx.x, y58 = blockIdx.y, b = blockIdx.z;
    int tid = threadIdx.x;
    int y = y58 - 1;
    if (y >= 0 && y < HH) {
        for (int idx = tid; idx < 64 * 58; idx += 256) {
            int c = idx / 58, px = idx % 58;
            int xx = px - 1;
            float v = 0.f;
            if (xx >= 0 && xx < WW)
                v = x[((size_t)(b * CIN_ + cblk * 64 + c)) * HW + y * WW + xx];
            tile[idx] = v;
        }
    } else {
        for (int idx = tid; idx < 64 * 58; idx += 256) tile[idx] = 0.f;
    }
    __syncthreads();
    __nv_bfloat16* dst = g_xpt + ((size_t)b * NP + y58 * 58) * 512 + cblk * 64;
    for (int idx = tid; idx < 58 * 64; idx += 256) {
        int px = idx >> 6, c = idx & 63;
        float v = tile[c * 58 + px];
        __nv_bfloat16 hi = __float2bfloat16(v);
        __nv_bfloat16 lo = __float2bfloat16(v - __bfloat162float(hi));
        dst[(size_t)px * 512 + c] = hi;
        dst[(size_t)px * 512 + 256 + c] = lo;
    }
}

// ---------------------------------------------------------------------------
// Loaders for conv kernel (512 threads)
// ---------------------------------------------------------------------------
__device__ __forceinline__ void load_A(int q, unsigned abuf,
                                       const __nv_bfloat16* Abase, int tid) {
    int row = tid >> 2;
    int ub  = (tid & 3) * 2;
    const char* arow = (const char*)(Abase + (size_t)row * 6912 + q * 64);
#pragma unroll
    for (int u = 0; u < 2; ++u)
        cpa16(abuf + SWZ(row * 128 + (ub + u) * 16), arow + (ub + u) * 16, 16);
}

__device__ __forceinline__ int group_c0(int g) {
    int cq = g / 3, kb = g % 3;
    return ((kb == 1) ? 256 : 0) + cq * 64;
}

// load one 1/9 slice (42 rows) of group gg's B super-tile
__device__ __forceinline__ void load_Bslice(int gg, int j, unsigned bbuf,
                                            const __nv_bfloat16* Bbase,
                                            int n0, int tid) {
    if (tid < 336) {
        int r = j * 42 + (tid >> 3);
        if (r < BSUP_ROWS) {
            int c0 = group_c0(gg);
            int n = n0 + r;
            bool ok = (n < NP);
            const char* src = ok ? (const char*)(Bbase + (size_t)n * 512 + c0)
                                 : (const char*)Bbase;
            unsigned sz = ok ? 16u : 0u;
            cpa16(bbuf + SWZ(r * 128 + (tid & 7) * 16), src + (tid & 7) * 16, sz);
        }
    }
}

// load full B super-tile (prologue)
__device__ __forceinline__ void load_Bfull(int gg, unsigned bbuf,
                                           const __nv_bfloat16* Bbase,
                                           int n0, int tid) {
    int c0 = group_c0(gg);
#pragma unroll
    for (int k = 0; k < 6; ++k) {
        int r = (tid >> 3) + k * 64;
        if (r < BSUP_ROWS) {
            int n = n0 + r;
            bool ok = (n < NP);
            const char* src = ok ? (const char*)(Bbase + (size_t)n * 512 + c0)
                                 : (const char*)Bbase;
            unsigned sz = ok ? 16u : 0u;
            cpa16(bbuf + SWZ(r * 128 + (tid & 7) * 16), src + (tid & 7) * 16, sz);
        }
    }
}

// ---------------------------------------------------------------------------
// Kernel 4: HMMA implicit-GEMM conv. grid (13, 2, 32), 512 threads.
// CTA: 128 oc x 256 px. Warp grid 4(M)x4(N), warp tile 32x64.
// A: 4-stage pipeline (16KB tiles). B: per-group 374-row super-tile,
// double-buffered, reused across the 9 kernel shifts via ldsm base offset.
// ---------------------------------------------------------------------------
__global__ __launch_bounds__(512, 1)
void conv_mma_kernel(float* __restrict__ out) {
    extern __shared__ __align__(1024) char smem[];
    const unsigned sbase = (unsigned)__cvta_generic_to_shared(smem);
    const int tid  = threadIdx.x;
    const int lane = tid & 31, wid = tid >> 5;
    const int n0   = blockIdx.x * 256;
    const int ocb  = blockIdx.y;
    const int b    = blockIdx.z;
    const int e    = g_expert[b];

    const __nv_bfloat16* Abase = g_A + (size_t)(e * 2 + ocb) * 128 * 6912;
    const __nv_bfloat16* Bbase = g_xpt + (size_t)b * NP * 512;

    const unsigned abufs[4] = { sbase, sbase + A_TILE_B,
                                sbase + 2 * A_TILE_B, sbase + 3 * A_TILE_B };
    const unsigned bbufs[2] = { sbase + BBUF_OFF, sbase + BBUF_OFF + BSUP_B };

    float acc[64];
#pragma unroll
    for (int i = 0; i < 64; ++i) acc[i] = 0.f;

    // warp / lane geometry: 4(M) x 4(N) warps, warp tile 32(M) x 64(N)
    const int wm = wid & 3, wn = wid >> 2;
    const int m0 = wm * 32, n0w = wn * 64;
    const int g  = lane >> 3, lr = lane & 7;
    const unsigned a_off0 = (unsigned)((m0 + (g & 1) * 8 + lr) * 128 + (g >> 1) * 16);
    const unsigned b_off0 = (unsigned)((n0w + (g >> 1) * 8 + lr) * 128 + (g & 1) * 16);

    // prologue: c0 = {B0 full, A0}, c1 = {A1}, c2 = {A2}
    load_Bfull(0, bbufs[0], Bbase, n0, tid);
    load_A(0, abufs[0], Abase, tid);
    asm volatile("cp.async.commit_group;" ::: "memory");
    load_A(1, abufs[1], Abase, tid);
    asm volatile("cp.async.commit_group;" ::: "memory");
    load_A(2, abufs[2], Abase, tid);
    asm volatile("cp.async.commit_group;" ::: "memory");

    for (int t = 0; t < KCH; ++t) {
        const int grp = t / 9;
        const int j   = t - grp * 9;              // k1k2
        const int shift = (j / 3) * 58 + (j % 3);

        if (t < KCH - 2)
            asm volatile("cp.async.wait_group 2;" ::: "memory");
        else if (t == KCH - 2)
            asm volatile("cp.async.wait_group 1;" ::: "memory");
        else
            asm volatile("cp.async.wait_group 0;" ::: "memory");
        __syncthreads();

        // prefetch: A(t+3) + B-slice j of group grp+1, one commit
        if (t + 3 < KCH) {
            load_A(t + 3, abufs[(t + 3) & 3], Abase, tid);
            if (grp + 1 < 12)
                load_Bslice(grp + 1, j, bbufs[(grp + 1) & 1], Bbase, n0, tid);
            asm volatile("cp.async.commit_group;" ::: "memory");
        }

        const unsigned ab = abufs[t & 3];
        const unsigned bb = bbufs[grp & 1];
        const unsigned bsh = b_off0 + shift * 128;
#pragma unroll
        for (int ks = 0; ks < 4; ++ks) {
            unsigned ar[8], br[16];
#pragma unroll
            for (int mt = 0; mt < 2; ++mt)
                ldsm_x4(ar + mt * 4, ab + SWZ(a_off0 + mt * 2048 + ks * 32));
#pragma unroll
            for (int ntp = 0; ntp < 4; ++ntp)
                ldsm_x4(br + ntp * 4, bb + SWZ(bsh + ntp * 2048 + ks * 32));
#pragma unroll
            for (int mt = 0; mt < 2; ++mt)
#pragma unroll
                for (int nt = 0; nt < 8; ++nt) {
                    int bi = (nt >> 1) * 4 + (nt & 1) * 2;
                    mma_bf16(acc + (mt * 8 + nt) * 4, ar + mt * 4,
                             br[bi], br[bi + 1]);
                }
        }
    }

    // --- epilogue: predicated direct stores ---
    const int qrow = lane >> 2;
    const int qc   = (lane & 3) * 2;
    const size_t ob = (size_t)b * COUT_ * HW;
#pragma unroll
    for (int mt = 0; mt < 2; ++mt) {
        const int mA = ocb * 128 + m0 + mt * 16 + qrow;
        const int mB = mA + 8;
#pragma unroll
        for (int nt = 0; nt < 8; ++nt) {
            const float* a4 = acc + (mt * 8 + nt) * 4;
            int p0 = n0 + n0w + nt * 8 + qc;
            int p1 = p0 + 1;
            int y0 = p0 / 58, x0 = p0 % 58;
            int y1 = p1 / 58, x1 = p1 % 58;
            bool v0 = (y0 < HH) && (x0 < WW);
            bool v1 = (y1 < HH) && (x1 < WW);
            if (v0) out[ob + ((size_t)mA * HH + y0) * WW + x0] = a4[0];
            if (v1) out[ob + ((size_t)mA * HH + y1) * WW + x1] = a4[1];
            if (v0) out[ob + ((size_t)mB * HH + y0) * WW + x0] = a4[2];
            if (v1) out[ob + ((size_t)mB * HH + y1) * WW + x1] = a4[3];
        }
    }
}

// ---------------------------------------------------------------------------
extern "C" void kernel_launch(void* const* d_in, const int* in_sizes, int n_in,
                              void* d_out, int out_size) {
    const float* x      = (const float*)d_in[0];
    const float* scores = (const float*)d_in[1];
    const float* weight = (const float*)d_in[2];
    const float* lora_A = (const float*)d_in[3];
    const float* lora_B = (const float*)d_in[4];
    float* out = (float*)d_out;

    cudaFuncSetAttribute(conv_mma_kernel,
                         cudaFuncAttributeMaxDynamicSharedMemorySize, SMEM_TOTAL);

    expert_kernel<<<1, 32>>>(scores);

    int total = E_ * COUT_ * M_PER_OC;          // 2,949,120
    abuild_kernel<<<total / 256, 256>>>(weight, lora_A, lora_B);

    dim3 xg(4, 58, B_);
    xprep_kernel<<<xg, 256>>>(x);

    dim3 cg(NTILES, 2, B_);
    conv_mma_kernel<<<cg, 512, SMEM_TOTAL>>>(out);
}